// round 10
// baseline (speedup 1.0000x reference)
#include <cuda_runtime.h>
#include <math.h>
#include <stdint.h>

#define T_TOK 8192
#define CDIM  1024
#define HDIM  4096
#define NEXP  8
#define TM    128
#define TN    256
#define MAXTILES 136
#define HROWS_MAX (MAXTILES * TM)
#define NSTAGE 4
#define KSTG   32
#define A_STG_BYTES (TM * KSTG * 4)          // 16384 (two 8KB k16 sub-buffers)
#define B_STG_BYTES (TN * KSTG * 4)          // 32768 (two 16KB k16 sub-buffers)

// ---------------- device scratch ----------------
__device__ int   g_cnt[NEXP];
__device__ int   g_off[NEXP];
__device__ int   g_tok[NEXP * T_TOK];
__device__ float g_wt [NEXP * T_TOK];
__device__ int   g_tile_e[MAXTILES];
__device__ int   g_tile_l[MAXTILES];
__device__ int   g_ntiles;
__device__ int   g_done;
__device__ float g_X[(size_t)HROWS_MAX * CDIM];      // gathered x, tf32-rounded
__device__ float g_H[(size_t)HROWS_MAX * HDIM];      // activations, tf32-rounded
__device__ float g_W1[(size_t)NEXP * HDIM * CDIM];   // tf32-rounded weights
__device__ float g_W2[(size_t)NEXP * CDIM * HDIM];

// ---------------- helpers ----------------
__device__ __forceinline__ unsigned int f2tf32(float f) {
    unsigned int r;
    asm("cvt.rna.tf32.f32 %0, %1;" : "=r"(r) : "f"(f));
    return r;
}
__device__ __forceinline__ float rna_tf32(float f) { return __uint_as_float(f2tf32(f)); }

__device__ __forceinline__ uint32_t smem_u32(const void* p) {
    uint32_t a;
    asm("{ .reg .u64 t; cvta.to.shared.u64 t, %1; cvt.u32.u64 %0, t; }" : "=r"(a) : "l"(p));
    return a;
}
__device__ __forceinline__ void cpasync16(uint32_t dst, const float* src) {
    asm volatile("cp.async.cg.shared.global [%0], [%1], 16;" :: "r"(dst), "l"(src));
}
#define CP_COMMIT()  asm volatile("cp.async.commit_group;" ::: "memory")
#define CP_WAIT(n)   asm volatile("cp.async.wait_group %0;" :: "n"(n) : "memory")

__device__ __forceinline__ void mma_tf32(float c[4], unsigned int a0, unsigned int a1,
                                         unsigned int a2, unsigned int a3,
                                         unsigned int b0, unsigned int b1) {
    asm volatile(
        "mma.sync.aligned.m16n8k8.row.col.f32.tf32.tf32.f32 "
        "{%0,%1,%2,%3}, {%4,%5,%6,%7}, {%8,%9}, {%0,%1,%2,%3};"
        : "+f"(c[0]), "+f"(c[1]), "+f"(c[2]), "+f"(c[3])
        : "r"(a0), "r"(a1), "r"(a2), "r"(a3), "r"(b0), "r"(b1));
}

__device__ __forceinline__ float gelu_tanh(float v) {
    float u = v + 0.044715f * v * v * v;
    return 0.5f * v * (1.0f + tanhf(0.7978845608028654f * u));
}

// ---------------- weight conversion (+ counter resets), one kernel ----------------
__global__ void convw_all(const float* __restrict__ w1, const float* __restrict__ w2) {
    if (blockIdx.x == 0) {
        if (threadIdx.x < NEXP) g_cnt[threadIdx.x] = 0;
        if (threadIdx.x == NEXP) g_done = 0;
    }
    const size_t half = (size_t)(NEXP * HDIM * CDIM) / 4;   // float4 count per weight
    size_t i = (size_t)blockIdx.x * 256 + threadIdx.x;
    const float4* src;
    float4* dst;
    if (i < half) { src = (const float4*)w1; dst = (float4*)g_W1; }
    else          { src = (const float4*)w2; dst = (float4*)g_W2; i -= half; }
    float4 v = src[i];
    v.x = rna_tf32(v.x); v.y = rna_tf32(v.y); v.z = rna_tf32(v.z); v.w = rna_tf32(v.w);
    dst[i] = v;
}

// ---------------- router (+ fused scheduler via completion counter) ----------------
__global__ void router_kernel(const float* __restrict__ x,
                              const float* __restrict__ gw) {
    __shared__ float xs[CDIM];
    __shared__ float lg[NEXP];
    const int t = blockIdx.x, tid = threadIdx.x;
    ((float4*)xs)[tid] = ((const float4*)(x + (size_t)t * CDIM))[tid];
    __syncthreads();
    const int e = tid >> 5, lane = tid & 31;
    const float* w = gw + e * CDIM;
    float s = 0.f;
    for (int i = lane * 4; i < CDIM; i += 128) {
        float4 a = *(const float4*)(xs + i);
        float4 b = *(const float4*)(w + i);
        s += a.x * b.x + a.y * b.y + a.z * b.z + a.w * b.w;
    }
    #pragma unroll
    for (int o = 16; o; o >>= 1) s += __shfl_xor_sync(0xffffffffu, s, o);
    if (lane == 0) lg[e] = s;
    __syncthreads();
    if (tid == 0) {
        float m = lg[0];
        #pragma unroll
        for (int i = 1; i < NEXP; i++) m = fmaxf(m, lg[i]);
        float p[NEXP]; float S = 0.f;
        #pragma unroll
        for (int i = 0; i < NEXP; i++) { p[i] = expf(lg[i] - m); S += p[i]; }
        #pragma unroll
        for (int i = 0; i < NEXP; i++) p[i] /= S;
        int i1 = 0;
        #pragma unroll
        for (int i = 1; i < NEXP; i++) if (p[i] > p[i1]) i1 = i;
        int i2 = (i1 == 0) ? 1 : 0;
        #pragma unroll
        for (int i = 0; i < NEXP; i++) { if (i == i1) continue; if (p[i] > p[i2]) i2 = i; }
        float denom = p[i1] + p[i2] + 1e-8f;
        float wa = p[i1] / denom, wb = p[i2] / denom;
        int pos = atomicAdd(&g_cnt[i1], 1);
        g_tok[i1 * T_TOK + pos] = t; g_wt[i1 * T_TOK + pos] = wa;
        pos = atomicAdd(&g_cnt[i2], 1);
        g_tok[i2 * T_TOK + pos] = t; g_wt[i2 * T_TOK + pos] = wb;

        __threadfence();
        int old = atomicAdd(&g_done, 1);
        if (old == T_TOK - 1) {
            int acc = 0, nt = 0;
            for (int ee = 0; ee < NEXP; ee++) {
                g_off[ee] = acc;
                int c = g_cnt[ee];
                int k = (c + TM - 1) / TM;
                for (int i = 0; i < k; i++) { g_tile_e[nt] = ee; g_tile_l[nt] = i; nt++; }
                acc += k * TM;
            }
            g_ntiles = nt;
            __threadfence();
        }
    }
}

// gather + rna-round x rows into padded per-expert segments (zero padding)
__global__ void gather_kernel(const float* __restrict__ x) {
    const int row = blockIdx.x;
    const int tile = row >> 7;
    if (tile >= g_ntiles) return;
    const int e = g_tile_e[tile];
    const int local = g_tile_l[tile] * TM + (row & 127);
    float4* dst = (float4*)(g_X + (size_t)row * CDIM);
    if (local < g_cnt[e]) {
        const float4* src = (const float4*)(x + (size_t)g_tok[e * T_TOK + local] * CDIM);
        float4 v = src[threadIdx.x];
        v.x = rna_tf32(v.x); v.y = rna_tf32(v.y); v.z = rna_tf32(v.z); v.w = rna_tf32(v.w);
        dst[threadIdx.x] = v;
    } else {
        dst[threadIdx.x] = make_float4(0.f, 0.f, 0.f, 0.f);
    }
}

// ---------------- grouped GEMM, mma.sync tf32, cp.async pipeline ----------------
// CTA tile 128x256, 8 warps as 2(m) x 4(n), warp tile 64x64 (acc 128 regs).
// KSTG=32 (two k16 sub-buffers, 64B row stride, conflict-free), NSTAGE=4,
// stage loop unrolled by 4 so ALL buffer indices are compile-time constants.
// Accounting (produce-after-sync): before wait at stage s, commits = 3+s.
// CP_WAIT(2) => complete >= s+1 => group for stage s has landed.  (R9 bug:
// wait(3) only guaranteed groups 0..s-1.)  PRODUCE goes right after the
// barrier so loads fly during the MMA burst; its target (s+3)&3 = (s-1)&3
// was consumed at stage s-1, protected by this stage's __syncthreads.
// smem: 1KB ctrl | A 4x16KB | B 4x32KB = 197632 B. 1 CTA/SM.
#define FFN_SMEM (1024 + NSTAGE * (A_STG_BYTES + B_STG_BYTES))

template <int KDIM, bool FFN1>
__global__ void __launch_bounds__(256, 1) ffn_gemm(const float* __restrict__ bias,
                                                   float* __restrict__ outp) {
    extern __shared__ char smem[];
    const int tile = blockIdx.x;
    if (tile >= g_ntiles) return;

    const float* Aglb = FFN1 ? g_X  : g_H;    // device-side symbol refs
    const float* Bglb = FFN1 ? g_W1 : g_W2;

    const int e     = g_tile_e[tile];
    const int l     = g_tile_l[tile];
    const int cnt   = g_cnt[e];
    const int r0    = l * TM;
    const int valid = min(TM, cnt - r0);
    const int NB    = FFN1 ? HDIM : CDIM;
    const int n0    = blockIdx.y * TN;
    const float* Bexp = Bglb + (size_t)e * KDIM * NB;
    const float* be   = bias + e * NB;
    const int hbase   = g_off[e] + r0;
    const int tid = threadIdx.x, wid = tid >> 5, lane = tid & 31;

    int*   tok_s = (int*)smem;
    float* wt_s  = (float*)(smem + 512);
    unsigned int* Asm = (unsigned int*)(smem + 1024);
    unsigned int* Bsm = (unsigned int*)(smem + 1024 + NSTAGE * A_STG_BYTES);
    const uint32_t Abase_u = smem_u32(Asm);
    const uint32_t Bbase_u = smem_u32(Bsm);

    if (tid < TM) {
        bool v = tid < valid;
        int idx = e * T_TOK + r0 + tid;
        tok_s[tid] = v ? g_tok[idx] : 0;
        wt_s[tid]  = v ? g_wt[idx]  : 0.f;
    }
    __syncthreads();

    // cp.async mapping for one 32-k stage:
    // A: 128 rows x 8 chunks = 1024 (4/thread). B: 256 x 8 = 2048 (8/thread).
    // chunk c: row=c>>3, cw=c&7, sub=cw>>2, q=cw&3; dst = sub*sub_bytes + row*64 + q*16
    const float* aS[4]; uint32_t aD[4];
    #pragma unroll
    for (int i = 0; i < 4; i++) {
        const int c = tid + 256 * i;
        const int row = c >> 3, cw = c & 7;
        aS[i] = Aglb + (size_t)(hbase + row) * KDIM + cw * 4;
        aD[i] = Abase_u + (cw >> 2) * (A_STG_BYTES / 2) + row * 64 + (cw & 3) * 16;
    }
    const float* bS[8]; uint32_t bD[8];
    #pragma unroll
    for (int i = 0; i < 8; i++) {
        const int c = tid + 256 * i;
        const int row = c >> 3, cw = c & 7;
        bS[i] = Bexp + (size_t)(n0 + row) * KDIM + cw * 4;
        bD[i] = Bbase_u + (cw >> 2) * (B_STG_BYTES / 2) + row * 64 + (cw & 3) * 16;
    }

    #define PRODUCE(bufi, kof) do { \
        const uint32_t _oa = (bufi) * A_STG_BYTES; \
        const uint32_t _ob = (bufi) * B_STG_BYTES; \
        _Pragma("unroll") \
        for (int _i = 0; _i < 4; _i++) cpasync16(aD[_i] + _oa, aS[_i] + (kof)); \
        _Pragma("unroll") \
        for (int _i = 0; _i < 8; _i++) cpasync16(bD[_i] + _ob, bS[_i] + (kof)); \
        CP_COMMIT(); \
    } while (0)

    const int wm = (wid & 1) * 64;        // warp m offset (0/64)
    const int wn = (wid >> 1) * 64;       // warp n offset (0/64/128/192)
    const int g  = lane >> 2, tg = lane & 3;

    float acc[4][8][4];
    #pragma unroll
    for (int i = 0; i < 4; i++)
        #pragma unroll
        for (int j = 0; j < 8; j++)
            #pragma unroll
            for (int q = 0; q < 4; q++) acc[i][j][q] = 0.f;

    const int NSTG = KDIM / KSTG;         // 32 (FFN1) or 128 (FFN2): both % 4 == 0
    PRODUCE(0, 0);
    PRODUCE(1, KSTG);
    PRODUCE(2, 2 * KSTG);

    #pragma unroll 1
    for (int sb = 0; sb < NSTG; sb += 4) {
        #pragma unroll
        for (int u = 0; u < 4; u++) {      // buf = u : compile-time constant
            const int s = sb + u;
            CP_WAIT(2);                    // commits = 3+s; complete >= s+1
            __syncthreads();

            if (s + 3 < NSTG) PRODUCE((u + 3) & 3, (s + 3) * KSTG);
            else CP_COMMIT();              // keep group accounting uniform

            #pragma unroll
            for (int sub = 0; sub < 2; sub++) {
                const unsigned int* Ab = Asm + u * (A_STG_BYTES / 4) + sub * (A_STG_BYTES / 8);
                const unsigned int* Bb = Bsm + u * (B_STG_BYTES / 4) + sub * (B_STG_BYTES / 8);

                uint4 aF[4][2];
                #pragma unroll
                for (int i = 0; i < 4; i++) {
                    const int r1 = wm + i * 16 + g;
                    aF[i][0] = *(const uint4*)(Ab + r1 * 16 + tg * 4);
                    aF[i][1] = *(const uint4*)(Ab + (r1 + 8) * 16 + tg * 4);
                }
                #pragma unroll
                for (int j = 0; j < 8; j++) {
                    const int nb = wn + j * 8 + g;
                    const uint4 bF = *(const uint4*)(Bb + nb * 16 + tg * 4);
                    #pragma unroll
                    for (int i = 0; i < 4; i++) {
                        mma_tf32(acc[i][j], aF[i][0].x, aF[i][1].x, aF[i][0].y, aF[i][1].y,
                                 bF.x, bF.y);
                        mma_tf32(acc[i][j], aF[i][0].z, aF[i][1].z, aF[i][0].w, aF[i][1].w,
                                 bF.z, bF.w);
                    }
                }
            }
        }
    }

    // -------- epilogue --------
    #pragma unroll
    for (int i = 0; i < 4; i++) {
        #pragma unroll
        for (int half = 0; half < 2; half++) {
            const int r = wm + i * 16 + g + half * 8;
            if (FFN1) {
                float* hrow = g_H + (size_t)(hbase + r) * HDIM;
                #pragma unroll
                for (int j = 0; j < 8; j++) {
                    const int n = n0 + wn + j * 8 + tg * 2;
                    float2 v;
                    v.x = rna_tf32(gelu_tanh(acc[i][j][half * 2 + 0] + be[n]));
                    v.y = rna_tf32(gelu_tanh(acc[i][j][half * 2 + 1] + be[n + 1]));
                    *(float2*)(hrow + n) = v;
                }
            } else if (r < valid) {
                const int tok = tok_s[r];
                const float w = wt_s[r];
                float* orow = outp + (size_t)tok * CDIM;
                #pragma unroll
                for (int j = 0; j < 8; j++) {
                    const int n = n0 + wn + j * 8 + tg * 2;
                    atomicAdd(orow + n,     w * (acc[i][j][half * 2 + 0] + be[n]));
                    atomicAdd(orow + n + 1, w * (acc[i][j][half * 2 + 1] + be[n + 1]));
                }
            }
        }
    }
    #undef PRODUCE
}

// ---------------- launch ----------------
extern "C" void kernel_launch(void* const* d_in, const int* in_sizes, int n_in,
                              void* d_out, int out_size) {
    const float* x  = (const float*)d_in[0];
    const float* gw = (const float*)d_in[1];
    const float* w1 = (const float*)d_in[2];
    const float* b1 = (const float*)d_in[3];
    const float* w2 = (const float*)d_in[4];
    const float* b2 = (const float*)d_in[5];
    float* out = (float*)d_out;

    cudaFuncSetAttribute(ffn_gemm<CDIM, true >, cudaFuncAttributeMaxDynamicSharedMemorySize, FFN_SMEM);
    cudaFuncSetAttribute(ffn_gemm<HDIM, false>, cudaFuncAttributeMaxDynamicSharedMemorySize, FFN_SMEM);

    cudaMemsetAsync(out, 0, (size_t)T_TOK * CDIM * sizeof(float));          // launch 0
    convw_all<<<2 * (NEXP * HDIM * CDIM) / 1024, 256>>>(w1, w2);            // launch 1
    router_kernel<<<T_TOK, 256>>>(x, gw);                                   // launch 2
    gather_kernel<<<MAXTILES * TM, 256>>>(x);                               // launch 3
    ffn_gemm<CDIM, true ><<<dim3(MAXTILES, HDIM / TN), 256, FFN_SMEM>>>(b1, nullptr);  // 4 (ncu)
    ffn_gemm<HDIM, false><<<dim3(MAXTILES, CDIM / TN), 256, FFN_SMEM>>>(b2, out);      // 5
}

// round 11
// speedup vs baseline: 1.1465x; 1.1465x over previous
#include <cuda_runtime.h>
#include <math.h>
#include <stdint.h>

#define T_TOK 8192
#define CDIM  1024
#define HDIM  4096
#define NEXP  8
#define TM    128
#define TNB   128                            // CTA tile N
#define MAXTILES 136
#define HROWS_MAX (MAXTILES * TM)
#define NSTAGE 3
#define KSTG   32
#define A_STG_BYTES (TM * KSTG * 4)          // 16384 (two 8KB k16 sub-buffers)
#define B_STG_BYTES (TNB * KSTG * 4)         // 16384

// ---------------- device scratch ----------------
__device__ int   g_cnt[NEXP];
__device__ int   g_off[NEXP];
__device__ int   g_tok[NEXP * T_TOK];
__device__ float g_wt [NEXP * T_TOK];
__device__ int   g_tile_e[MAXTILES];
__device__ int   g_tile_l[MAXTILES];
__device__ int   g_ntiles;
__device__ int   g_done;
__device__ float g_X[(size_t)HROWS_MAX * CDIM];      // gathered x, tf32-rounded
__device__ float g_H[(size_t)HROWS_MAX * HDIM];      // activations, tf32-rounded
__device__ float g_W1[(size_t)NEXP * HDIM * CDIM];   // tf32-rounded weights
__device__ float g_W2[(size_t)NEXP * CDIM * HDIM];

// ---------------- helpers ----------------
__device__ __forceinline__ unsigned int f2tf32(float f) {
    unsigned int r;
    asm("cvt.rna.tf32.f32 %0, %1;" : "=r"(r) : "f"(f));
    return r;
}
__device__ __forceinline__ float rna_tf32(float f) { return __uint_as_float(f2tf32(f)); }

__device__ __forceinline__ uint32_t smem_u32(const void* p) {
    uint32_t a;
    asm("{ .reg .u64 t; cvta.to.shared.u64 t, %1; cvt.u32.u64 %0, t; }" : "=r"(a) : "l"(p));
    return a;
}
__device__ __forceinline__ void cpasync16(uint32_t dst, const float* src) {
    asm volatile("cp.async.cg.shared.global [%0], [%1], 16;" :: "r"(dst), "l"(src));
}
#define CP_COMMIT()  asm volatile("cp.async.commit_group;" ::: "memory")
#define CP_WAIT(n)   asm volatile("cp.async.wait_group %0;" :: "n"(n) : "memory")

__device__ __forceinline__ void mma_tf32(float c[4], unsigned int a0, unsigned int a1,
                                         unsigned int a2, unsigned int a3,
                                         unsigned int b0, unsigned int b1) {
    asm volatile(
        "mma.sync.aligned.m16n8k8.row.col.f32.tf32.tf32.f32 "
        "{%0,%1,%2,%3}, {%4,%5,%6,%7}, {%8,%9}, {%0,%1,%2,%3};"
        : "+f"(c[0]), "+f"(c[1]), "+f"(c[2]), "+f"(c[3])
        : "r"(a0), "r"(a1), "r"(a2), "r"(a3), "r"(b0), "r"(b1));
}

__device__ __forceinline__ float gelu_tanh(float v) {
    float u = v + 0.044715f * v * v * v;
    return 0.5f * v * (1.0f + tanhf(0.7978845608028654f * u));
}

// ---------------- weight conversion (+ counter resets), one kernel ----------------
__global__ void convw_all(const float* __restrict__ w1, const float* __restrict__ w2) {
    if (blockIdx.x == 0) {
        if (threadIdx.x < NEXP) g_cnt[threadIdx.x] = 0;
        if (threadIdx.x == NEXP) g_done = 0;
    }
    const size_t half = (size_t)(NEXP * HDIM * CDIM) / 4;   // float4 count per weight
    size_t i = (size_t)blockIdx.x * 256 + threadIdx.x;
    const float4* src;
    float4* dst;
    if (i < half) { src = (const float4*)w1; dst = (float4*)g_W1; }
    else          { src = (const float4*)w2; dst = (float4*)g_W2; i -= half; }
    float4 v = src[i];
    v.x = rna_tf32(v.x); v.y = rna_tf32(v.y); v.z = rna_tf32(v.z); v.w = rna_tf32(v.w);
    dst[i] = v;
}

// ---------------- router (+ fused scheduler via completion counter) ----------------
__global__ void router_kernel(const float* __restrict__ x,
                              const float* __restrict__ gw) {
    __shared__ float xs[CDIM];
    __shared__ float lg[NEXP];
    const int t = blockIdx.x, tid = threadIdx.x;
    ((float4*)xs)[tid] = ((const float4*)(x + (size_t)t * CDIM))[tid];
    __syncthreads();
    const int e = tid >> 5, lane = tid & 31;
    const float* w = gw + e * CDIM;
    float s = 0.f;
    for (int i = lane * 4; i < CDIM; i += 128) {
        float4 a = *(const float4*)(xs + i);
        float4 b = *(const float4*)(w + i);
        s += a.x * b.x + a.y * b.y + a.z * b.z + a.w * b.w;
    }
    #pragma unroll
    for (int o = 16; o; o >>= 1) s += __shfl_xor_sync(0xffffffffu, s, o);
    if (lane == 0) lg[e] = s;
    __syncthreads();
    if (tid == 0) {
        float m = lg[0];
        #pragma unroll
        for (int i = 1; i < NEXP; i++) m = fmaxf(m, lg[i]);
        float p[NEXP]; float S = 0.f;
        #pragma unroll
        for (int i = 0; i < NEXP; i++) { p[i] = expf(lg[i] - m); S += p[i]; }
        #pragma unroll
        for (int i = 0; i < NEXP; i++) p[i] /= S;
        int i1 = 0;
        #pragma unroll
        for (int i = 1; i < NEXP; i++) if (p[i] > p[i1]) i1 = i;
        int i2 = (i1 == 0) ? 1 : 0;
        #pragma unroll
        for (int i = 0; i < NEXP; i++) { if (i == i1) continue; if (p[i] > p[i2]) i2 = i; }
        float denom = p[i1] + p[i2] + 1e-8f;
        float wa = p[i1] / denom, wb = p[i2] / denom;
        int pos = atomicAdd(&g_cnt[i1], 1);
        g_tok[i1 * T_TOK + pos] = t; g_wt[i1 * T_TOK + pos] = wa;
        pos = atomicAdd(&g_cnt[i2], 1);
        g_tok[i2 * T_TOK + pos] = t; g_wt[i2 * T_TOK + pos] = wb;

        __threadfence();
        int old = atomicAdd(&g_done, 1);
        if (old == T_TOK - 1) {
            int acc = 0, nt = 0;
            for (int ee = 0; ee < NEXP; ee++) {
                g_off[ee] = acc;
                int c = g_cnt[ee];
                int k = (c + TM - 1) / TM;
                for (int i = 0; i < k; i++) { g_tile_e[nt] = ee; g_tile_l[nt] = i; nt++; }
                acc += k * TM;
            }
            g_ntiles = nt;
            __threadfence();
        }
    }
}

// gather + rna-round x rows into padded per-expert segments (zero padding)
__global__ void gather_kernel(const float* __restrict__ x) {
    const int row = blockIdx.x;
    const int tile = row >> 7;
    if (tile >= g_ntiles) return;
    const int e = g_tile_e[tile];
    const int local = g_tile_l[tile] * TM + (row & 127);
    float4* dst = (float4*)(g_X + (size_t)row * CDIM);
    if (local < g_cnt[e]) {
        const float4* src = (const float4*)(x + (size_t)g_tok[e * T_TOK + local] * CDIM);
        float4 v = src[threadIdx.x];
        v.x = rna_tf32(v.x); v.y = rna_tf32(v.y); v.z = rna_tf32(v.z); v.w = rna_tf32(v.w);
        dst[threadIdx.x] = v;
    } else {
        dst[threadIdx.x] = make_float4(0.f, 0.f, 0.f, 0.f);
    }
}

// ---------------- grouped GEMM, mma.sync tf32, cp.async pipeline ----------------
// CTA tile 128x128, 4 warps as 2(m) x 2(n), warp tile 64x64 (acc 128 regs).
// TWO CTAs PER SM (independent pipelines overlap each other's barriers/loads).
// KSTG=32 (two k16 sub-buffers, 64B row stride, conflict-free), NSTAGE=3.
// R6-proven loop: PRODUCE(s+2) -> wait(2) -> sync -> MMA -> sync.
// Accounting: commits before wait at stage s = 2 + (s+1) = s+3; wait(2) =>
// complete >= s+1 => stage-s data landed. Produce target (s+2)%3 = (s-1)%3
// was consumed at stage s-1 and released by its trailing __syncthreads.
// smem per CTA: 1KB ctrl | A 3x16KB | B 3x16KB = 99328 B; 2 CTAs = 198656 B.
#define FFN_SMEM (1024 + NSTAGE * (A_STG_BYTES + B_STG_BYTES))

template <int KDIM, bool FFN1>
__global__ void __launch_bounds__(128, 2) ffn_gemm(const float* __restrict__ bias,
                                                   float* __restrict__ outp) {
    extern __shared__ char smem[];
    const int tile = blockIdx.x;
    if (tile >= g_ntiles) return;

    const float* Aglb = FFN1 ? g_X  : g_H;    // device-side symbol refs
    const float* Bglb = FFN1 ? g_W1 : g_W2;

    const int e     = g_tile_e[tile];
    const int l     = g_tile_l[tile];
    const int cnt   = g_cnt[e];
    const int r0    = l * TM;
    const int valid = min(TM, cnt - r0);
    const int NB    = FFN1 ? HDIM : CDIM;
    const int n0    = blockIdx.y * TNB;
    const float* Bexp = Bglb + (size_t)e * KDIM * NB;
    const float* be   = bias + e * NB;
    const int hbase   = g_off[e] + r0;
    const int tid = threadIdx.x, wid = tid >> 5, lane = tid & 31;

    int*   tok_s = (int*)smem;
    float* wt_s  = (float*)(smem + 512);
    unsigned int* Asm = (unsigned int*)(smem + 1024);
    unsigned int* Bsm = (unsigned int*)(smem + 1024 + NSTAGE * A_STG_BYTES);
    const uint32_t Abase_u = smem_u32(Asm);
    const uint32_t Bbase_u = smem_u32(Bsm);

    {   // all 128 threads load token map
        bool v = tid < valid;
        int idx = e * T_TOK + r0 + tid;
        tok_s[tid] = v ? g_tok[idx] : 0;
        wt_s[tid]  = v ? g_wt[idx]  : 0.f;
    }
    __syncthreads();

    // cp.async mapping for one 32-k stage:
    // A: 128 rows x 8 chunks = 1024 (8/thread). B: 128 x 8 = 1024 (8/thread).
    // chunk c: row=c>>3, cw=c&7, sub=cw>>2, q=cw&3; dst = sub*8KB + row*64 + q*16
    const float* aS[8]; uint32_t aD[8];
    const float* bS[8]; uint32_t bD[8];
    #pragma unroll
    for (int i = 0; i < 8; i++) {
        const int c = tid + 128 * i;
        const int row = c >> 3, cw = c & 7;
        aS[i] = Aglb + (size_t)(hbase + row) * KDIM + cw * 4;
        aD[i] = Abase_u + (cw >> 2) * (A_STG_BYTES / 2) + row * 64 + (cw & 3) * 16;
        bS[i] = Bexp + (size_t)(n0 + row) * KDIM + cw * 4;
        bD[i] = Bbase_u + (cw >> 2) * (B_STG_BYTES / 2) + row * 64 + (cw & 3) * 16;
    }

    #define PRODUCE(bufi, kof) do { \
        const uint32_t _oa = (bufi) * A_STG_BYTES; \
        const uint32_t _ob = (bufi) * B_STG_BYTES; \
        _Pragma("unroll") \
        for (int _i = 0; _i < 8; _i++) cpasync16(aD[_i] + _oa, aS[_i] + (kof)); \
        _Pragma("unroll") \
        for (int _i = 0; _i < 8; _i++) cpasync16(bD[_i] + _ob, bS[_i] + (kof)); \
        CP_COMMIT(); \
    } while (0)

    const int wm = (wid & 1) * 64;        // warp m offset (0/64)
    const int wn = (wid >> 1) * 64;       // warp n offset (0/64)
    const int g  = lane >> 2, tg = lane & 3;

    float acc[4][8][4];
    #pragma unroll
    for (int i = 0; i < 4; i++)
        #pragma unroll
        for (int j = 0; j < 8; j++)
            #pragma unroll
            for (int q = 0; q < 4; q++) acc[i][j][q] = 0.f;

    const int NSTG = KDIM / KSTG;         // 32 (FFN1) or 128 (FFN2)
    PRODUCE(0, 0);
    PRODUCE(1, KSTG);

    int bufc = 0, bufp = 2;
    #pragma unroll 1
    for (int s = 0; s < NSTG; s++) {
        if (s + 2 < NSTG) PRODUCE(bufp, (s + 2) * KSTG);
        else CP_COMMIT();                 // keep group accounting uniform
        CP_WAIT(2);                       // commits = s+3; complete >= s+1
        __syncthreads();

        const unsigned int* AbS = Asm + bufc * (A_STG_BYTES / 4);
        const unsigned int* BbS = Bsm + bufc * (B_STG_BYTES / 4);
        #pragma unroll
        for (int sub = 0; sub < 2; sub++) {
            const unsigned int* Ab = AbS + sub * (A_STG_BYTES / 8);
            const unsigned int* Bb = BbS + sub * (B_STG_BYTES / 8);

            uint4 aF[4][2];
            #pragma unroll
            for (int i = 0; i < 4; i++) {
                const int r1 = wm + i * 16 + g;
                aF[i][0] = *(const uint4*)(Ab + r1 * 16 + tg * 4);
                aF[i][1] = *(const uint4*)(Ab + (r1 + 8) * 16 + tg * 4);
            }
            #pragma unroll
            for (int j = 0; j < 8; j++) {
                const int nb = wn + j * 8 + g;
                const uint4 bF = *(const uint4*)(Bb + nb * 16 + tg * 4);
                #pragma unroll
                for (int i = 0; i < 4; i++) {
                    mma_tf32(acc[i][j], aF[i][0].x, aF[i][1].x, aF[i][0].y, aF[i][1].y,
                             bF.x, bF.y);
                    mma_tf32(acc[i][j], aF[i][0].z, aF[i][1].z, aF[i][0].w, aF[i][1].w,
                             bF.z, bF.w);
                }
            }
        }
        __syncthreads();

        bufc = (bufc == NSTAGE - 1) ? 0 : bufc + 1;
        bufp = (bufp == NSTAGE - 1) ? 0 : bufp + 1;
    }

    // -------- epilogue --------
    #pragma unroll
    for (int i = 0; i < 4; i++) {
        #pragma unroll
        for (int half = 0; half < 2; half++) {
            const int r = wm + i * 16 + g + half * 8;
            if (FFN1) {
                float* hrow = g_H + (size_t)(hbase + r) * HDIM;
                #pragma unroll
                for (int j = 0; j < 8; j++) {
                    const int n = n0 + wn + j * 8 + tg * 2;
                    float2 v;
                    v.x = rna_tf32(gelu_tanh(acc[i][j][half * 2 + 0] + be[n]));
                    v.y = rna_tf32(gelu_tanh(acc[i][j][half * 2 + 1] + be[n + 1]));
                    *(float2*)(hrow + n) = v;
                }
            } else if (r < valid) {
                const int tok = tok_s[r];
                const float w = wt_s[r];
                float* orow = outp + (size_t)tok * CDIM;
                #pragma unroll
                for (int j = 0; j < 8; j++) {
                    const int n = n0 + wn + j * 8 + tg * 2;
                    atomicAdd(orow + n,     w * (acc[i][j][half * 2 + 0] + be[n]));
                    atomicAdd(orow + n + 1, w * (acc[i][j][half * 2 + 1] + be[n + 1]));
                }
            }
        }
    }
    #undef PRODUCE
}

// ---------------- launch ----------------
extern "C" void kernel_launch(void* const* d_in, const int* in_sizes, int n_in,
                              void* d_out, int out_size) {
    const float* x  = (const float*)d_in[0];
    const float* gw = (const float*)d_in[1];
    const float* w1 = (const float*)d_in[2];
    const float* b1 = (const float*)d_in[3];
    const float* w2 = (const float*)d_in[4];
    const float* b2 = (const float*)d_in[5];
    float* out = (float*)d_out;

    cudaFuncSetAttribute(ffn_gemm<CDIM, true >, cudaFuncAttributeMaxDynamicSharedMemorySize, FFN_SMEM);
    cudaFuncSetAttribute(ffn_gemm<HDIM, false>, cudaFuncAttributeMaxDynamicSharedMemorySize, FFN_SMEM);

    cudaMemsetAsync(out, 0, (size_t)T_TOK * CDIM * sizeof(float));          // launch 0
    convw_all<<<2 * (NEXP * HDIM * CDIM) / 1024, 256>>>(w1, w2);            // launch 1
    router_kernel<<<T_TOK, 256>>>(x, gw);                                   // launch 2
    gather_kernel<<<MAXTILES * TM, 256>>>(x);                               // launch 3
    ffn_gemm<CDIM, true ><<<dim3(MAXTILES, HDIM / TNB), 128, FFN_SMEM>>>(b1, nullptr); // 4 (ncu)
    ffn_gemm<HDIM, false><<<dim3(MAXTILES, CDIM / TNB), 128, FFN_SMEM>>>(b2, out);     // 5
}

// round 12
// speedup vs baseline: 1.1657x; 1.0167x over previous
#include <cuda_runtime.h>
#include <math.h>
#include <stdint.h>

#define T_TOK 8192
#define CDIM  1024
#define HDIM  4096
#define NEXP  8
#define TM    128
#define TNB   128                            // CTA tile N
#define MAXTILES 136
#define HROWS_MAX (MAXTILES * TM)
#define NSTAGE 3
#define KSTG   32
#define A_STG_BYTES (TM * KSTG * 4)          // 16384 (two 8KB k16 sub-buffers)
#define B_STG_BYTES (TNB * KSTG * 4)         // 16384

// ---------------- device scratch ----------------
__device__ int   g_cnt[NEXP];
__device__ int   g_off[NEXP];
__device__ int   g_tok[NEXP * T_TOK];
__device__ float g_wt [NEXP * T_TOK];
__device__ int   g_tile_e[MAXTILES];
__device__ int   g_tile_l[MAXTILES];
__device__ int   g_ntiles;
__device__ int   g_done;
__device__ float g_X[(size_t)HROWS_MAX * CDIM];      // gathered x, tf32-rounded
__device__ float g_H[(size_t)HROWS_MAX * HDIM];      // activations, tf32-rounded
__device__ float g_W1[(size_t)NEXP * HDIM * CDIM];   // tf32-rounded weights
__device__ float g_W2[(size_t)NEXP * CDIM * HDIM];

// ---------------- helpers ----------------
__device__ __forceinline__ unsigned int f2tf32(float f) {
    unsigned int r;
    asm("cvt.rna.tf32.f32 %0, %1;" : "=r"(r) : "f"(f));
    return r;
}
__device__ __forceinline__ float rna_tf32(float f) { return __uint_as_float(f2tf32(f)); }

__device__ __forceinline__ uint32_t smem_u32(const void* p) {
    uint32_t a;
    asm("{ .reg .u64 t; cvta.to.shared.u64 t, %1; cvt.u32.u64 %0, t; }" : "=r"(a) : "l"(p));
    return a;
}
__device__ __forceinline__ void cpasync16(uint32_t dst, const float* src) {
    asm volatile("cp.async.cg.shared.global [%0], [%1], 16;" :: "r"(dst), "l"(src));
}
#define CP_COMMIT()  asm volatile("cp.async.commit_group;" ::: "memory")
#define CP_WAIT(n)   asm volatile("cp.async.wait_group %0;" :: "n"(n) : "memory")

__device__ __forceinline__ void mma_tf32(float c[4], unsigned int a0, unsigned int a1,
                                         unsigned int a2, unsigned int a3,
                                         unsigned int b0, unsigned int b1) {
    asm volatile(
        "mma.sync.aligned.m16n8k8.row.col.f32.tf32.tf32.f32 "
        "{%0,%1,%2,%3}, {%4,%5,%6,%7}, {%8,%9}, {%0,%1,%2,%3};"
        : "+f"(c[0]), "+f"(c[1]), "+f"(c[2]), "+f"(c[3])
        : "r"(a0), "r"(a1), "r"(a2), "r"(a3), "r"(b0), "r"(b1));
}

__device__ __forceinline__ float gelu_tanh(float v) {
    float u = v + 0.044715f * v * v * v;
    return 0.5f * v * (1.0f + tanhf(0.7978845608028654f * u));
}

// ---------------- weight conversion (+ counter resets), one kernel ----------------
__global__ void convw_all(const float* __restrict__ w1, const float* __restrict__ w2) {
    if (blockIdx.x == 0) {
        if (threadIdx.x < NEXP) g_cnt[threadIdx.x] = 0;
        if (threadIdx.x == NEXP) g_done = 0;
    }
    const size_t half = (size_t)(NEXP * HDIM * CDIM) / 4;   // float4 count per weight
    size_t i = (size_t)blockIdx.x * 256 + threadIdx.x;
    const float4* src;
    float4* dst;
    if (i < half) { src = (const float4*)w1; dst = (float4*)g_W1; }
    else          { src = (const float4*)w2; dst = (float4*)g_W2; i -= half; }
    float4 v = src[i];
    v.x = rna_tf32(v.x); v.y = rna_tf32(v.y); v.z = rna_tf32(v.z); v.w = rna_tf32(v.w);
    dst[i] = v;
}

// ---------------- router (+ fused scheduler via completion counter) ----------------
__global__ void router_kernel(const float* __restrict__ x,
                              const float* __restrict__ gw) {
    __shared__ float xs[CDIM];
    __shared__ float lg[NEXP];
    const int t = blockIdx.x, tid = threadIdx.x;
    ((float4*)xs)[tid] = ((const float4*)(x + (size_t)t * CDIM))[tid];
    __syncthreads();
    const int e = tid >> 5, lane = tid & 31;
    const float* w = gw + e * CDIM;
    float s = 0.f;
    for (int i = lane * 4; i < CDIM; i += 128) {
        float4 a = *(const float4*)(xs + i);
        float4 b = *(const float4*)(w + i);
        s += a.x * b.x + a.y * b.y + a.z * b.z + a.w * b.w;
    }
    #pragma unroll
    for (int o = 16; o; o >>= 1) s += __shfl_xor_sync(0xffffffffu, s, o);
    if (lane == 0) lg[e] = s;
    __syncthreads();
    if (tid == 0) {
        float m = lg[0];
        #pragma unroll
        for (int i = 1; i < NEXP; i++) m = fmaxf(m, lg[i]);
        float p[NEXP]; float S = 0.f;
        #pragma unroll
        for (int i = 0; i < NEXP; i++) { p[i] = expf(lg[i] - m); S += p[i]; }
        #pragma unroll
        for (int i = 0; i < NEXP; i++) p[i] /= S;
        int i1 = 0;
        #pragma unroll
        for (int i = 1; i < NEXP; i++) if (p[i] > p[i1]) i1 = i;
        int i2 = (i1 == 0) ? 1 : 0;
        #pragma unroll
        for (int i = 0; i < NEXP; i++) { if (i == i1) continue; if (p[i] > p[i2]) i2 = i; }
        float denom = p[i1] + p[i2] + 1e-8f;
        float wa = p[i1] / denom, wb = p[i2] / denom;
        int pos = atomicAdd(&g_cnt[i1], 1);
        g_tok[i1 * T_TOK + pos] = t; g_wt[i1 * T_TOK + pos] = wa;
        pos = atomicAdd(&g_cnt[i2], 1);
        g_tok[i2 * T_TOK + pos] = t; g_wt[i2 * T_TOK + pos] = wb;

        __threadfence();
        int old = atomicAdd(&g_done, 1);
        if (old == T_TOK - 1) {
            int acc = 0, nt = 0;
            for (int ee = 0; ee < NEXP; ee++) {
                g_off[ee] = acc;
                int c = g_cnt[ee];
                int k = (c + TM - 1) / TM;
                for (int i = 0; i < k; i++) { g_tile_e[nt] = ee; g_tile_l[nt] = i; nt++; }
                acc += k * TM;
            }
            g_ntiles = nt;
            __threadfence();
        }
    }
}

// gather + rna-round x rows into padded per-expert segments (zero padding)
__global__ void gather_kernel(const float* __restrict__ x) {
    const int row = blockIdx.x;
    const int tile = row >> 7;
    if (tile >= g_ntiles) return;
    const int e = g_tile_e[tile];
    const int local = g_tile_l[tile] * TM + (row & 127);
    float4* dst = (float4*)(g_X + (size_t)row * CDIM);
    if (local < g_cnt[e]) {
        const float4* src = (const float4*)(x + (size_t)g_tok[e * T_TOK + local] * CDIM);
        float4 v = src[threadIdx.x];
        v.x = rna_tf32(v.x); v.y = rna_tf32(v.y); v.z = rna_tf32(v.z); v.w = rna_tf32(v.w);
        dst[threadIdx.x] = v;
    } else {
        dst[threadIdx.x] = make_float4(0.f, 0.f, 0.f, 0.f);
    }
}

// ---------------- grouped GEMM, mma.sync tf32, cp.async pipeline ----------------
// CTA tile 128x128, 4 warps as 2(m) x 2(n), warp tile 64x64. 2 CTAs/SM.
// NSTAGE=3, KSTG=32 (two k16 sub-buffers). ONE barrier per stage:
//   wait(1) -> sync -> MMA(sub0) -> PRODUCE(s+2) -> MMA(sub1)
// Safety: produce targets (s+2)%3 = (s-1)%3; every warp passed the stage-s
// barrier only after finishing its stage-(s-1) MMAs, so that buffer is free.
// Accounting: commits at stage-s wait = 2+s; block s = commit #(s+1);
// wait(1) => complete >= s+1 => stage-s data landed. Latency slack ~1.5 stages.
// smem per CTA: 1KB ctrl | A 3x16KB | B 3x16KB = 99328 B; 2 CTAs/SM.
#define FFN_SMEM (1024 + NSTAGE * (A_STG_BYTES + B_STG_BYTES))

template <int KDIM, bool FFN1>
__global__ void __launch_bounds__(128, 2) ffn_gemm(const float* __restrict__ bias,
                                                   float* __restrict__ outp) {
    extern __shared__ char smem[];
    const int tile = blockIdx.x;
    if (tile >= g_ntiles) return;

    const float* Aglb = FFN1 ? g_X  : g_H;    // device-side symbol refs
    const float* Bglb = FFN1 ? g_W1 : g_W2;

    const int e     = g_tile_e[tile];
    const int l     = g_tile_l[tile];
    const int cnt   = g_cnt[e];
    const int r0    = l * TM;
    const int valid = min(TM, cnt - r0);
    const int NB    = FFN1 ? HDIM : CDIM;
    const int n0    = blockIdx.y * TNB;
    const float* Bexp = Bglb + (size_t)e * KDIM * NB;
    const float* be   = bias + e * NB;
    const int hbase   = g_off[e] + r0;
    const int tid = threadIdx.x, wid = tid >> 5, lane = tid & 31;

    int*   tok_s = (int*)smem;
    float* wt_s  = (float*)(smem + 512);
    unsigned int* Asm = (unsigned int*)(smem + 1024);
    unsigned int* Bsm = (unsigned int*)(smem + 1024 + NSTAGE * A_STG_BYTES);
    const uint32_t Abase_u = smem_u32(Asm);
    const uint32_t Bbase_u = smem_u32(Bsm);

    {   // all 128 threads load token map
        bool v = tid < valid;
        int idx = e * T_TOK + r0 + tid;
        tok_s[tid] = v ? g_tok[idx] : 0;
        wt_s[tid]  = v ? g_wt[idx]  : 0.f;
    }
    __syncthreads();

    // cp.async mapping for one 32-k stage:
    // A: 128 rows x 8 chunks = 1024 (8/thread). B: 128 x 8 = 1024 (8/thread).
    // chunk c: row=c>>3, cw=c&7, sub=cw>>2, q=cw&3; dst = sub*8KB + row*64 + q*16
    const float* aS[8]; uint32_t aD[8];
    const float* bS[8]; uint32_t bD[8];
    #pragma unroll
    for (int i = 0; i < 8; i++) {
        const int c = tid + 128 * i;
        const int row = c >> 3, cw = c & 7;
        aS[i] = Aglb + (size_t)(hbase + row) * KDIM + cw * 4;
        aD[i] = Abase_u + (cw >> 2) * (A_STG_BYTES / 2) + row * 64 + (cw & 3) * 16;
        bS[i] = Bexp + (size_t)(n0 + row) * KDIM + cw * 4;
        bD[i] = Bbase_u + (cw >> 2) * (B_STG_BYTES / 2) + row * 64 + (cw & 3) * 16;
    }

    #define PRODUCE(bufi, kof) do { \
        const uint32_t _oa = (bufi) * A_STG_BYTES; \
        const uint32_t _ob = (bufi) * B_STG_BYTES; \
        _Pragma("unroll") \
        for (int _i = 0; _i < 8; _i++) cpasync16(aD[_i] + _oa, aS[_i] + (kof)); \
        _Pragma("unroll") \
        for (int _i = 0; _i < 8; _i++) cpasync16(bD[_i] + _ob, bS[_i] + (kof)); \
        CP_COMMIT(); \
    } while (0)

    const int wm = (wid & 1) * 64;        // warp m offset (0/64)
    const int wn = (wid >> 1) * 64;       // warp n offset (0/64)
    const int g  = lane >> 2, tg = lane & 3;

    float acc[4][8][4];
    #pragma unroll
    for (int i = 0; i < 4; i++)
        #pragma unroll
        for (int j = 0; j < 8; j++)
            #pragma unroll
            for (int q = 0; q < 4; q++) acc[i][j][q] = 0.f;

    #define MMA_SUB(Ab, Bb) do { \
        uint4 aF[4][2]; \
        _Pragma("unroll") \
        for (int i = 0; i < 4; i++) { \
            const int r1 = wm + i * 16 + g; \
            aF[i][0] = *(const uint4*)((Ab) + r1 * 16 + tg * 4); \
            aF[i][1] = *(const uint4*)((Ab) + (r1 + 8) * 16 + tg * 4); \
        } \
        _Pragma("unroll") \
        for (int j = 0; j < 8; j++) { \
            const int nb = wn + j * 8 + g; \
            const uint4 bF = *(const uint4*)((Bb) + nb * 16 + tg * 4); \
            _Pragma("unroll") \
            for (int i = 0; i < 4; i++) { \
                mma_tf32(acc[i][j], aF[i][0].x, aF[i][1].x, aF[i][0].y, aF[i][1].y, \
                         bF.x, bF.y); \
                mma_tf32(acc[i][j], aF[i][0].z, aF[i][1].z, aF[i][0].w, aF[i][1].w, \
                         bF.z, bF.w); \
            } \
        } \
    } while (0)

    const int NSTG = KDIM / KSTG;         // 32 (FFN1) or 128 (FFN2)
    PRODUCE(0, 0);
    PRODUCE(1, KSTG);

    int bufc = 0, bufp = 2;
    #pragma unroll 1
    for (int s = 0; s < NSTG; s++) {
        CP_WAIT(1);                       // commits = 2+s; complete >= s+1
        __syncthreads();                  // single barrier per stage

        const unsigned int* AbS = Asm + bufc * (A_STG_BYTES / 4);
        const unsigned int* BbS = Bsm + bufc * (B_STG_BYTES / 4);

        MMA_SUB(AbS, BbS);                               // sub 0

        if (s + 2 < NSTG) PRODUCE(bufp, (s + 2) * KSTG); // overlaps sub1 MMAs
        else CP_COMMIT();                 // keep group accounting uniform

        MMA_SUB(AbS + A_STG_BYTES / 8, BbS + B_STG_BYTES / 8);  // sub 1

        bufc = (bufc == NSTAGE - 1) ? 0 : bufc + 1;
        bufp = (bufp == NSTAGE - 1) ? 0 : bufp + 1;
    }

    // -------- epilogue --------
    #pragma unroll
    for (int i = 0; i < 4; i++) {
        #pragma unroll
        for (int half = 0; half < 2; half++) {
            const int r = wm + i * 16 + g + half * 8;
            if (FFN1) {
                float* hrow = g_H + (size_t)(hbase + r) * HDIM;
                #pragma unroll
                for (int j = 0; j < 8; j++) {
                    const int n = n0 + wn + j * 8 + tg * 2;
                    float2 v;
                    v.x = rna_tf32(gelu_tanh(acc[i][j][half * 2 + 0] + be[n]));
                    v.y = rna_tf32(gelu_tanh(acc[i][j][half * 2 + 1] + be[n + 1]));
                    *(float2*)(hrow + n) = v;
                }
            } else if (r < valid) {
                const int tok = tok_s[r];
                const float w = wt_s[r];
                float* orow = outp + (size_t)tok * CDIM;
                #pragma unroll
                for (int j = 0; j < 8; j++) {
                    const int n = n0 + wn + j * 8 + tg * 2;
                    atomicAdd(orow + n,     w * (acc[i][j][half * 2 + 0] + be[n]));
                    atomicAdd(orow + n + 1, w * (acc[i][j][half * 2 + 1] + be[n + 1]));
                }
            }
        }
    }
    #undef PRODUCE
    #undef MMA_SUB
}

// ---------------- launch ----------------
extern "C" void kernel_launch(void* const* d_in, const int* in_sizes, int n_in,
                              void* d_out, int out_size) {
    const float* x  = (const float*)d_in[0];
    const float* gw = (const float*)d_in[1];
    const float* w1 = (const float*)d_in[2];
    const float* b1 = (const float*)d_in[3];
    const float* w2 = (const float*)d_in[4];
    const float* b2 = (const float*)d_in[5];
    float* out = (float*)d_out;

    cudaFuncSetAttribute(ffn_gemm<CDIM, true >, cudaFuncAttributeMaxDynamicSharedMemorySize, FFN_SMEM);
    cudaFuncSetAttribute(ffn_gemm<HDIM, false>, cudaFuncAttributeMaxDynamicSharedMemorySize, FFN_SMEM);

    cudaMemsetAsync(out, 0, (size_t)T_TOK * CDIM * sizeof(float));          // launch 0
    convw_all<<<2 * (NEXP * HDIM * CDIM) / 1024, 256>>>(w1, w2);            // launch 1
    router_kernel<<<T_TOK, 256>>>(x, gw);                                   // launch 2
    gather_kernel<<<MAXTILES * TM, 256>>>(x);                               // launch 3
    ffn_gemm<CDIM, true ><<<dim3(MAXTILES, HDIM / TNB), 128, FFN_SMEM>>>(b1, nullptr); // 4 (ncu)
    ffn_gemm<HDIM, false><<<dim3(MAXTILES, CDIM / TNB), 128, FFN_SMEM>>>(b2, out);     // 5
}